// round 16
// baseline (speedup 1.0000x reference)
#include <cuda_runtime.h>
#include <cuda_bf16.h>
#include <cstdint>
#include <cstddef>

#define DM 19
#define HID 512
#define NH 8
#define DH 64
#define BB 16
#define LL 1024
#define NTOK (BB*LL)
#define QT 128

#define OUT_ELEMS   (NTOK*DM)
#define ATTN_ELEMS  ((size_t)BB*NH*LL*LL)

// ---- scratch ----
__device__ __align__(256) __nv_bfloat16 g_qs[(size_t)BB*NH*LL*128];  // [bh][l][hi64|lo64]
__device__ __align__(256) __nv_bfloat16 g_ks[(size_t)BB*NH*LL*128];
__device__ __align__(256) float         g_v [(size_t)BB*NH*LL*DH];
__device__ __align__(256) __nv_bfloat16 g_vT[(size_t)BB*NH*DH*LL];   // [bh][d][l]
__device__ __align__(256) float         g_ctx[(size_t)NTOK*HID];
__device__ __align__(256) float         g_inv[(size_t)BB*NH*LL];     // 1/rowsum

// ---- helpers ----
__device__ __forceinline__ uint32_t s2u(const void* p) {
    uint32_t a;
    asm("{ .reg .u64 t; cvta.to.shared.u64 t, %1; cvt.u32.u64 %0, t; }" : "=r"(a) : "l"(p));
    return a;
}
__device__ __forceinline__ void cp16(uint32_t dst, const void* src) {
    asm volatile("cp.async.cg.shared.global [%0], [%1], 16;"
                 :: "r"(dst), "l"(__cvta_generic_to_global(src)));
}
#define CP_COMMIT() asm volatile("cp.async.commit_group;" ::: "memory")
#define CP_WAIT(n)  asm volatile("cp.async.wait_group %0;" :: "n"(n) : "memory")

#define MMA16816(c, a0, a1, a2, a3, b0, b1)                                   \
    asm volatile("mma.sync.aligned.m16n8k16.row.col.f32.bf16.bf16.f32 "       \
        "{%0,%1,%2,%3}, {%4,%5,%6,%7}, {%8,%9}, {%0,%1,%2,%3};"               \
        : "+f"((c)[0]), "+f"((c)[1]), "+f"((c)[2]), "+f"((c)[3])              \
        : "r"(a0), "r"(a1), "r"(a2), "r"(a3), "r"(b0), "r"(b1))

__device__ __forceinline__ void ldsm4(uint32_t& r0, uint32_t& r1, uint32_t& r2,
                                      uint32_t& r3, uint32_t addr) {
    asm volatile("ldmatrix.sync.aligned.m8n8.x4.shared.b16 {%0,%1,%2,%3}, [%4];"
                 : "=r"(r0), "=r"(r1), "=r"(r2), "=r"(r3) : "r"(addr));
}

__device__ __forceinline__ uint32_t pbf2(float a, float b) {
    __nv_bfloat162 t = __floats2bfloat162_rn(a, b);
    return *reinterpret_cast<uint32_t*>(&t);
}

// =====================================================================
// Kernel 1: QKV projections. Q,K -> split bf16 [hi|lo]; V -> fp32
// =====================================================================
__global__ void proj_kernel(const float* __restrict__ Xq, const float* __restrict__ Xk,
                            const float* __restrict__ Xv,
                            const float* __restrict__ Wq, const float* __restrict__ Wk,
                            const float* __restrict__ Wv,
                            const float* __restrict__ bq, const float* __restrict__ bk,
                            const float* __restrict__ bv) {
    __shared__ float sW[DM*HID];
    __shared__ float sX[32*20];
    const int which = blockIdx.y;
    const float* X    = (which == 0) ? Xq : (which == 1) ? Xk : Xv;
    const float* W    = (which == 0) ? Wq : (which == 1) ? Wk : Wv;
    const float* bias = (which == 0) ? bq : (which == 1) ? bk : bv;

    const int t = threadIdx.x;
    for (int i = t; i < DM*HID; i += 256) sW[i] = W[i];
    const int base = blockIdx.x * 32;
    for (int i = t; i < 32*DM; i += 256) {
        int r = i / DM, m = i - r*DM;
        sX[r*20 + m] = X[(size_t)(base + r)*DM + m];
    }
    __syncthreads();

    const int bidx = base >> 10;
    const int lbase = base & 1023;
    #pragma unroll
    for (int cc = 0; cc < 2; cc++) {
        const int c = t + cc*256;
        const int h = c >> 6, d = c & 63;
        const float bval = bias[c];
        if (which < 2) {
            __nv_bfloat16* dp = (which == 0 ? g_qs : g_ks)
                + ((size_t)(bidx*NH + h)*LL + lbase)*128 + d;
            for (int r = 0; r < 32; r++) {
                float acc = bval;
                #pragma unroll
                for (int m = 0; m < DM; m++) acc += sX[r*20 + m] * sW[m*HID + c];
                __nv_bfloat16 hi = __float2bfloat16(acc);
                __nv_bfloat16 lo = __float2bfloat16(acc - __bfloat162float(hi));
                dp[(size_t)r*128]      = hi;
                dp[(size_t)r*128 + 64] = lo;
            }
        } else {
            float* dp = g_v + ((size_t)(bidx*NH + h)*LL + lbase)*DH + d;
            for (int r = 0; r < 32; r++) {
                float acc = bval;
                #pragma unroll
                for (int m = 0; m < DM; m++) acc += sX[r*20 + m] * sW[m*HID + c];
                dp[(size_t)r*DH] = acc;
            }
        }
    }
}

// =====================================================================
// Kernel 1b: V transpose  g_v[bh][l][d] fp32 -> g_vT[bh][d][l] bf16
// =====================================================================
__global__ void transpose_v_kernel() {
    __shared__ float ts[128*65];
    const int t = threadIdx.x;
    const int bh = blockIdx.y;
    const int lbase = blockIdx.x * 128;
    const float* src = g_v + ((size_t)bh*LL + lbase)*DH;
    #pragma unroll
    for (int j = 0; j < 8; j++) {
        int idx = t + j*256;
        int r = idx >> 4, d4 = (idx & 15)*4;
        float4 a = *(const float4*)(src + (size_t)r*DH + d4);
        ts[r*65 + d4 + 0] = a.x; ts[r*65 + d4 + 1] = a.y;
        ts[r*65 + d4 + 2] = a.z; ts[r*65 + d4 + 3] = a.w;
    }
    __syncthreads();
    #pragma unroll
    for (int j = 0; j < 4; j++) {
        int idx = t + j*256;
        int d = idx >> 4, c8 = (idx & 15)*8;
        uint4 o;
        o.x = pbf2(ts[(c8+0)*65 + d], ts[(c8+1)*65 + d]);
        o.y = pbf2(ts[(c8+2)*65 + d], ts[(c8+3)*65 + d]);
        o.z = pbf2(ts[(c8+4)*65 + d], ts[(c8+5)*65 + d]);
        o.w = pbf2(ts[(c8+6)*65 + d], ts[(c8+7)*65 + d]);
        *(uint4*)(g_vT + ((size_t)bh*DH + d)*LL + lbase + c8) = o;
    }
}

// =====================================================================
// Kernel 2: mma.sync attention. grid (8, 128), 512 threads, smem 208896
// ldmatrix fragment loads. Warp pair per 16-q tile; warp owns half chunk.
// =====================================================================
#define SQ_  0u
#define SK0_ 51200u
#define SK1_ 76800u
#define SV0_ 102400u
#define SV1_ 111616u
#define SM0_ 120832u
#define SM1_ 155648u
#define SP_  190464u
#define ATT_SMEM 208896

__device__ __forceinline__ void load_kvm(uint32_t sb, int buf, int cb, int bh, int b,
                                         int qbase, const int* __restrict__ mask, int t) {
    const uint32_t sk = sb + (buf ? SK1_ : SK0_);
    const uint32_t sv = sb + (buf ? SV1_ : SV0_);
    const uint32_t sm = sb + (buf ? SM1_ : SM0_);
    const __nv_bfloat16* ks = g_ks + ((size_t)bh*LL + cb)*128;
    #pragma unroll
    for (int j = 0; j < 3; j++) {                        // K: 64 keys x 24 f4
        int idx = t + j*512; int key = idx/24, p = idx%24; int sf = (p < 8) ? p : p - 8;
        cp16(sk + key*400 + p*16, ks + (size_t)key*128 + sf*8);
    }
    const __nv_bfloat16* vt = g_vT + (size_t)bh*DH*LL + cb;
    {                                                    // V: 64 d x 8 f4
        int d = t >> 3, p = t & 7;
        cp16(sv + d*144 + p*16, vt + (size_t)d*LL + p*8);
    }
    const int* mp = mask + ((size_t)b*LL + qbase)*LL + cb;
    #pragma unroll
    for (int j = 0; j < 4; j++) {                        // mask: 128 q x 16 f4
        int idx = t + j*512; int row = idx >> 4, p = idx & 15;
        cp16(sm + row*272 + p*16, mp + (size_t)row*LL + p*4);
    }
}

__global__ __launch_bounds__(512, 1)
void attn_kernel(const int* __restrict__ mask, float* __restrict__ attn_out) {
    extern __shared__ char smem[];
    __shared__ float ssum[2][QT];
    const uint32_t sb = s2u(smem);
    const int t = threadIdx.x;
    const int wid = t >> 5, lane = t & 31;
    const int g = lane >> 2, m = lane & 3;
    const int qt = wid >> 1, half = wid & 1;
    const int bh = blockIdx.y, b = bh >> 3, h = bh & 7;
    const int qbase = blockIdx.x * QT;
    const int r1 = qt*16 + g, r2 = r1 + 8;
    const float INVSCALE = 0.13258252147247766f;   // sqrt(9/512)

    // ldmatrix per-lane addressing
    const int lrow  = (lane & 7) + ((lane >> 3) & 1)*8;   // A: row in 16-row tile
    const int lcol  = (lane >> 4)*16;                     // A: 16B col half
    const int brow  = (lane & 7) + (lane >> 4)*8;         // B: row (key/d) in 16-row pair
    const int bcol  = ((lane >> 3) & 1)*16;               // B: 16B col half

    // prologue
    {
        const __nv_bfloat16* qs = g_qs + ((size_t)bh*LL + qbase)*128;
        #pragma unroll
        for (int j = 0; j < 6; j++) {                    // Q: [hi|lo|hi], 128 q x 24 f4
            int idx = t + j*512; int row = idx/24, p = idx%24; int sf = (p < 16) ? p : p - 16;
            cp16(sb + SQ_ + row*400 + p*16, qs + (size_t)row*128 + sf*8);
        }
        load_kvm(sb, 0, 0, bh, b, qbase, mask, t);
        CP_COMMIT();
        load_kvm(sb, 1, 64, bh, b, qbase, mask, t);
        CP_COMMIT();
    }

    uint32_t* Pp = (uint32_t*)(smem + SP_);
    const uint32_t qaddr = sb + SQ_ + (qt*16 + lrow)*400 + lcol;
    const uint32_t paddr = sb + SP_ + (qt*16 + lrow)*144 + lcol;
    float cacc[8][4] = {};
    float sumA = 0.f, sumB = 0.f;
    const size_t bhrow = (size_t)bh*LL + qbase;

    for (int tt = 0; tt < 16; tt++) {
        if (tt == 15) { CP_WAIT(0); } else { CP_WAIT(1); }
        __syncthreads();
        const int buf = tt & 1;
        const uint32_t kaddr = sb + (buf ? SK1_ : SK0_) + (half*32 + brow)*400 + bcol;
        const uint32_t vaddr = sb + (buf ? SV1_ : SV0_) + brow*144 + bcol;
        const int* Mp = (const int*)(smem + (buf ? SM1_ : SM0_));
        const int cb = tt*64;

        // ---- scores: own key half, 4 n-tiles x 12 k-steps, ldmatrix loads ----
        float acc[4][4] = {};
        #pragma unroll
        for (int ks = 0; ks < 12; ks++) {
            uint32_t a0, a1, a2, a3;
            ldsm4(a0, a1, a2, a3, qaddr + ks*32);
            uint32_t b0, b1, b2, b3;
            ldsm4(b0, b1, b2, b3, kaddr + ks*32);             // nt 0,1
            MMA16816(acc[0], a0, a1, a2, a3, b0, b1);
            MMA16816(acc[1], a0, a1, a2, a3, b2, b3);
            ldsm4(b0, b1, b2, b3, kaddr + 16*400 + ks*32);    // nt 2,3
            MMA16816(acc[2], a0, a1, a2, a3, b0, b1);
            MMA16816(acc[3], a0, a1, a2, a3, b2, b3);
        }
        // ---- mask + exp + sums + attn(e) store + P(bf16) ----
        #pragma unroll
        for (int nt = 0; nt < 4; nt++) {
            const int keyc = half*32 + nt*8 + 2*m;
            int2 mA = *(const int2*)(Mp + r1*68 + keyc);
            int2 mB = *(const int2*)(Mp + r2*68 + keyc);
            float e00 = mA.x ? 0.f : __expf(acc[nt][0]*INVSCALE);
            float e01 = mA.y ? 0.f : __expf(acc[nt][1]*INVSCALE);
            float e10 = mB.x ? 0.f : __expf(acc[nt][2]*INVSCALE);
            float e11 = mB.y ? 0.f : __expf(acc[nt][3]*INVSCALE);
            sumA += e00 + e01; sumB += e10 + e11;
            *(float2*)(attn_out + (bhrow + r1)*LL + cb + keyc) = make_float2(e00, e01);
            *(float2*)(attn_out + (bhrow + r2)*LL + cb + keyc) = make_float2(e10, e11);
            Pp[r1*36 + (half*4 + nt)*4 + m] = pbf2(e00, e01);
            Pp[r2*36 + (half*4 + nt)*4 + m] = pbf2(e10, e11);
        }
        __syncwarp();
        // ---- PV: own 2 k-steps, all 8 d-tiles, ldmatrix loads ----
        #pragma unroll
        for (int ksl = 0; ksl < 2; ksl++) {
            const int ks = half*2 + ksl;
            uint32_t a0, a1, a2, a3;
            ldsm4(a0, a1, a2, a3, paddr + ks*32);
            #pragma unroll
            for (int nt2 = 0; nt2 < 4; nt2++) {
                uint32_t b0, b1, b2, b3;
                ldsm4(b0, b1, b2, b3, vaddr + nt2*16*144 + ks*32);
                MMA16816(cacc[nt2*2+0], a0, a1, a2, a3, b0, b1);
                MMA16816(cacc[nt2*2+1], a0, a1, a2, a3, b2, b3);
            }
        }
        __syncthreads();
        if (tt + 2 < 16) { load_kvm(sb, buf, (tt+2)*64, bh, b, qbase, mask, t); CP_COMMIT(); }
    }

    // ---- row sums ----
    sumA += __shfl_xor_sync(~0u, sumA, 1); sumA += __shfl_xor_sync(~0u, sumA, 2);
    sumB += __shfl_xor_sync(~0u, sumB, 1); sumB += __shfl_xor_sync(~0u, sumB, 2);
    if (m == 0) { ssum[half][r1] = sumA; ssum[half][r2] = sumB; }
    __syncthreads();

    // ---- combine ctx halves through smem (K buffers free) ----
    float* cbuf = (float*)(smem + SK0_);    // pitch 66
    if (half == 0) {
        #pragma unroll
        for (int nt = 0; nt < 8; nt++) {
            *(float2*)(cbuf + r1*66 + nt*8 + 2*m) = make_float2(cacc[nt][0], cacc[nt][1]);
            *(float2*)(cbuf + r2*66 + nt*8 + 2*m) = make_float2(cacc[nt][2], cacc[nt][3]);
        }
    }
    __syncthreads();
    if (half == 1) {
        const float invA = 1.0f / (ssum[0][r1] + ssum[1][r1]);
        const float invB = 1.0f / (ssum[0][r2] + ssum[1][r2]);
        if (m == 0) {
            g_inv[bhrow + r1] = invA;
            g_inv[bhrow + r2] = invB;
        }
        float* c1p = g_ctx + ((size_t)b*LL + qbase + r1)*HID + h*DH;
        float* c2p = g_ctx + ((size_t)b*LL + qbase + r2)*HID + h*DH;
        #pragma unroll
        for (int nt = 0; nt < 8; nt++) {
            float2 p1 = *(float2*)(cbuf + r1*66 + nt*8 + 2*m);
            float2 p2 = *(float2*)(cbuf + r2*66 + nt*8 + 2*m);
            *(float2*)(c1p + nt*8 + 2*m) = make_float2((p1.x + cacc[nt][0])*invA,
                                                       (p1.y + cacc[nt][1])*invA);
            *(float2*)(c2p + nt*8 + 2*m) = make_float2((p2.x + cacc[nt][2])*invB,
                                                       (p2.y + cacc[nt][3])*invB);
        }
    }
}

// =====================================================================
// Kernel 2b: attn *= 1/rowsum  (in-place stream, DRAM-roofline)
// =====================================================================
__global__ void attn_scale_kernel(float* __restrict__ attn) {
    const size_t i = ((size_t)blockIdx.x*256 + threadIdx.x);
    const size_t base = i*4;
    const float inv = g_inv[base >> 10];
    float4 v = *(float4*)(attn + base);
    v.x *= inv; v.y *= inv; v.z *= inv; v.w *= inv;
    *(float4*)(attn + base) = v;
}

// =====================================================================
// Kernel 3: out = LN(ctx @ Wo + bo + residual). 1024 thr, 32 tokens/block
// =====================================================================
__global__ void outproj_kernel(const float* __restrict__ Qin, const float* __restrict__ Wo,
                               const float* __restrict__ bo, const float* __restrict__ lng,
                               const float* __restrict__ lnb, float* __restrict__ out) {
    extern __shared__ float osm[];
    float* sWo = osm;                 // 512*19
    float* scx = sWo + HID*DM;        // 32*512
    float* sx  = scx + 32*HID;        // 32*20
    const int t = threadIdx.x, warp = t >> 5, lane = t & 31;
    for (int i = t; i < HID*DM; i += 1024) sWo[i] = Wo[i];
    const int n = blockIdx.x*32 + warp;
    #pragma unroll
    for (int k = 0; k < 4; k++)
        *(float4*)(scx + warp*HID + lane*4 + 128*k) =
            *(const float4*)(g_ctx + (size_t)n*HID + lane*4 + 128*k);
    __syncthreads();

    float x = 0.f;
    if (lane < DM) {
        float a0 = 0.f, a1 = 0.f, a2 = 0.f, a3 = 0.f;
        const float* cs = scx + warp*HID;
        for (int i = 0; i < HID; i += 4) {
            a0 += cs[i+0]*sWo[(i+0)*DM + lane];
            a1 += cs[i+1]*sWo[(i+1)*DM + lane];
            a2 += cs[i+2]*sWo[(i+2)*DM + lane];
            a3 += cs[i+3]*sWo[(i+3)*DM + lane];
        }
        x = (a0+a1) + (a2+a3) + bo[lane] + Qin[(size_t)n*DM + lane];
        sx[warp*20 + lane] = x;
    }
    __syncwarp();
    if (lane < DM) {
        float mu = 0.f;
        #pragma unroll
        for (int j = 0; j < DM; j++) mu += sx[warp*20 + j];
        mu *= (1.0f/19.0f);
        float var = 0.f;
        #pragma unroll
        for (int j = 0; j < DM; j++) { float d = sx[warp*20 + j] - mu; var += d*d; }
        var *= (1.0f/19.0f);
        out[(size_t)n*DM + lane] = (x - mu)*rsqrtf(var + 1e-5f)*lng[lane] + lnb[lane];
    }
}

// =====================================================================
// Kernel 4: residual = Q
// =====================================================================
__global__ void copy_res_kernel(const float* __restrict__ Qin, float* __restrict__ dst) {
    const size_t i = ((size_t)blockIdx.x*256 + threadIdx.x)*4;
    *(float4*)(dst + i) = *(const float4*)(Qin + i);
}

// =====================================================================
extern "C" void kernel_launch(void* const* d_in, const int* in_sizes, int n_in,
                              void* d_out, int out_size) {
    const float* Q   = (const float*)d_in[0];
    const float* K   = (const float*)d_in[1];
    const float* V   = (const float*)d_in[2];
    const int*  mask = (const int*)d_in[3];
    const float* Wq  = (const float*)d_in[4];
    const float* bq  = (const float*)d_in[5];
    const float* Wk  = (const float*)d_in[6];
    const float* bk  = (const float*)d_in[7];
    const float* Wv  = (const float*)d_in[8];
    const float* bv  = (const float*)d_in[9];
    const float* Wo  = (const float*)d_in[10];
    const float* bo  = (const float*)d_in[11];
    const float* lng = (const float*)d_in[12];
    const float* lnb = (const float*)d_in[13];

    float* out  = (float*)d_out;
    float* attn = out + OUT_ELEMS;
    float* res  = attn + ATTN_ELEMS;

    cudaFuncSetAttribute(attn_kernel, cudaFuncAttributeMaxDynamicSharedMemorySize, ATT_SMEM);
    const int OUT_SMEM = (HID*DM + 32*HID + 32*20) * (int)sizeof(float);   // 107008
    cudaFuncSetAttribute(outproj_kernel, cudaFuncAttributeMaxDynamicSharedMemorySize, OUT_SMEM);

    proj_kernel<<<dim3(NTOK/32, 3), 256>>>(Q, K, V, Wq, Wk, Wv, bq, bk, bv);
    transpose_v_kernel<<<dim3(LL/128, BB*NH), 256>>>();
    attn_kernel<<<dim3(LL/QT, BB*NH), 512, ATT_SMEM>>>(mask, attn);
    attn_scale_kernel<<<(int)(ATTN_ELEMS/4/256), 256>>>(attn);
    outproj_kernel<<<NTOK/32, 1024, OUT_SMEM>>>(Q, Wo, bo, lng, lnb, out);
    copy_res_kernel<<<OUT_ELEMS/4/256, 256>>>(Q, res);
}

// round 17
// speedup vs baseline: 1.1047x; 1.1047x over previous
#include <cuda_runtime.h>
#include <cuda_bf16.h>
#include <cstdint>
#include <cstddef>

#define DM 19
#define HID 512
#define NH 8
#define DH 64
#define BB 16
#define LL 1024
#define NTOK (BB*LL)
#define QT 128

#define OUT_ELEMS   (NTOK*DM)
#define ATTN_ELEMS  ((size_t)BB*NH*LL*LL)

// ---- scratch ----
__device__ __align__(256) __nv_bfloat16 g_qs[(size_t)BB*NH*LL*128];  // [bh][l][hi64|lo64]
__device__ __align__(256) __nv_bfloat16 g_ks[(size_t)BB*NH*LL*128];
__device__ __align__(256) float         g_v [(size_t)BB*NH*LL*DH];
__device__ __align__(256) __nv_bfloat16 g_vT[(size_t)BB*NH*DH*LL];   // [bh][d][l]
__device__ __align__(256) float         g_ctx[(size_t)NTOK*HID];

// ---- helpers ----
__device__ __forceinline__ uint32_t s2u(const void* p) {
    uint32_t a;
    asm("{ .reg .u64 t; cvta.to.shared.u64 t, %1; cvt.u32.u64 %0, t; }" : "=r"(a) : "l"(p));
    return a;
}
__device__ __forceinline__ void cp16(uint32_t dst, const void* src) {
    asm volatile("cp.async.cg.shared.global [%0], [%1], 16;"
                 :: "r"(dst), "l"(__cvta_generic_to_global(src)));
}
#define CP_COMMIT() asm volatile("cp.async.commit_group;" ::: "memory")
#define CP_WAIT(n)  asm volatile("cp.async.wait_group %0;" :: "n"(n) : "memory")

#define MMA16816(c, a0, a1, a2, a3, b0, b1)                                   \
    asm volatile("mma.sync.aligned.m16n8k16.row.col.f32.bf16.bf16.f32 "       \
        "{%0,%1,%2,%3}, {%4,%5,%6,%7}, {%8,%9}, {%0,%1,%2,%3};"               \
        : "+f"((c)[0]), "+f"((c)[1]), "+f"((c)[2]), "+f"((c)[3])              \
        : "r"(a0), "r"(a1), "r"(a2), "r"(a3), "r"(b0), "r"(b1))

__device__ __forceinline__ void ldsm4(uint32_t& r0, uint32_t& r1, uint32_t& r2,
                                      uint32_t& r3, uint32_t addr) {
    asm volatile("ldmatrix.sync.aligned.m8n8.x4.shared.b16 {%0,%1,%2,%3}, [%4];"
                 : "=r"(r0), "=r"(r1), "=r"(r2), "=r"(r3) : "r"(addr));
}

__device__ __forceinline__ uint32_t pbf2(float a, float b) {
    __nv_bfloat162 t = __floats2bfloat162_rn(a, b);
    return *reinterpret_cast<uint32_t*>(&t);
}

// =====================================================================
// Kernel 1: QKV projections. Q,K -> split bf16 [hi|lo]; V -> fp32
// =====================================================================
__global__ void proj_kernel(const float* __restrict__ Xq, const float* __restrict__ Xk,
                            const float* __restrict__ Xv,
                            const float* __restrict__ Wq, const float* __restrict__ Wk,
                            const float* __restrict__ Wv,
                            const float* __restrict__ bq, const float* __restrict__ bk,
                            const float* __restrict__ bv) {
    __shared__ float sW[DM*HID];
    __shared__ float sX[32*20];
    const int which = blockIdx.y;
    const float* X    = (which == 0) ? Xq : (which == 1) ? Xk : Xv;
    const float* W    = (which == 0) ? Wq : (which == 1) ? Wk : Wv;
    const float* bias = (which == 0) ? bq : (which == 1) ? bk : bv;

    const int t = threadIdx.x;
    for (int i = t; i < DM*HID; i += 256) sW[i] = W[i];
    const int base = blockIdx.x * 32;
    for (int i = t; i < 32*DM; i += 256) {
        int r = i / DM, m = i - r*DM;
        sX[r*20 + m] = X[(size_t)(base + r)*DM + m];
    }
    __syncthreads();

    const int bidx = base >> 10;
    const int lbase = base & 1023;
    #pragma unroll
    for (int cc = 0; cc < 2; cc++) {
        const int c = t + cc*256;
        const int h = c >> 6, d = c & 63;
        const float bval = bias[c];
        if (which < 2) {
            __nv_bfloat16* dp = (which == 0 ? g_qs : g_ks)
                + ((size_t)(bidx*NH + h)*LL + lbase)*128 + d;
            for (int r = 0; r < 32; r++) {
                float acc = bval;
                #pragma unroll
                for (int m = 0; m < DM; m++) acc += sX[r*20 + m] * sW[m*HID + c];
                __nv_bfloat16 hi = __float2bfloat16(acc);
                __nv_bfloat16 lo = __float2bfloat16(acc - __bfloat162float(hi));
                dp[(size_t)r*128]      = hi;
                dp[(size_t)r*128 + 64] = lo;
            }
        } else {
            float* dp = g_v + ((size_t)(bidx*NH + h)*LL + lbase)*DH + d;
            for (int r = 0; r < 32; r++) {
                float acc = bval;
                #pragma unroll
                for (int m = 0; m < DM; m++) acc += sX[r*20 + m] * sW[m*HID + c];
                dp[(size_t)r*DH] = acc;
            }
        }
    }
}

// =====================================================================
// Kernel 1b: V transpose  g_v[bh][l][d] fp32 -> g_vT[bh][d][l] bf16
// =====================================================================
__global__ void transpose_v_kernel() {
    __shared__ float ts[128*65];
    const int t = threadIdx.x;
    const int bh = blockIdx.y;
    const int lbase = blockIdx.x * 128;
    const float* src = g_v + ((size_t)bh*LL + lbase)*DH;
    #pragma unroll
    for (int j = 0; j < 8; j++) {
        int idx = t + j*256;
        int r = idx >> 4, d4 = (idx & 15)*4;
        float4 a = *(const float4*)(src + (size_t)r*DH + d4);
        ts[r*65 + d4 + 0] = a.x; ts[r*65 + d4 + 1] = a.y;
        ts[r*65 + d4 + 2] = a.z; ts[r*65 + d4 + 3] = a.w;
    }
    __syncthreads();
    #pragma unroll
    for (int j = 0; j < 4; j++) {
        int idx = t + j*256;
        int d = idx >> 4, c8 = (idx & 15)*8;
        uint4 o;
        o.x = pbf2(ts[(c8+0)*65 + d], ts[(c8+1)*65 + d]);
        o.y = pbf2(ts[(c8+2)*65 + d], ts[(c8+3)*65 + d]);
        o.z = pbf2(ts[(c8+4)*65 + d], ts[(c8+5)*65 + d]);
        o.w = pbf2(ts[(c8+6)*65 + d], ts[(c8+7)*65 + d]);
        *(uint4*)(g_vT + ((size_t)bh*DH + d)*LL + lbase + c8) = o;
    }
}

// =====================================================================
// Kernel 2: mma.sync attention. grid (8, 128), 512 threads, smem 208896
// ldmatrix fragment loads; fused L2-resident normalization tail.
// =====================================================================
#define SQ_  0u
#define SK0_ 51200u
#define SK1_ 76800u
#define SV0_ 102400u
#define SV1_ 111616u
#define SM0_ 120832u
#define SM1_ 155648u
#define SP_  190464u
#define ATT_SMEM 208896

__device__ __forceinline__ void load_kvm(uint32_t sb, int buf, int cb, int bh, int b,
                                         int qbase, const int* __restrict__ mask, int t) {
    const uint32_t sk = sb + (buf ? SK1_ : SK0_);
    const uint32_t sv = sb + (buf ? SV1_ : SV0_);
    const uint32_t sm = sb + (buf ? SM1_ : SM0_);
    const __nv_bfloat16* ks = g_ks + ((size_t)bh*LL + cb)*128;
    #pragma unroll
    for (int j = 0; j < 3; j++) {                        // K: 64 keys x 24 f4
        int idx = t + j*512; int key = idx/24, p = idx%24; int sf = (p < 8) ? p : p - 8;
        cp16(sk + key*400 + p*16, ks + (size_t)key*128 + sf*8);
    }
    const __nv_bfloat16* vt = g_vT + (size_t)bh*DH*LL + cb;
    {                                                    // V: 64 d x 8 f4
        int d = t >> 3, p = t & 7;
        cp16(sv + d*144 + p*16, vt + (size_t)d*LL + p*8);
    }
    const int* mp = mask + ((size_t)b*LL + qbase)*LL + cb;
    #pragma unroll
    for (int j = 0; j < 4; j++) {                        // mask: 128 q x 16 f4
        int idx = t + j*512; int row = idx >> 4, p = idx & 15;
        cp16(sm + row*272 + p*16, mp + (size_t)row*LL + p*4);
    }
}

__global__ __launch_bounds__(512, 1)
void attn_kernel(const int* __restrict__ mask, float* __restrict__ attn_out) {
    extern __shared__ char smem[];
    __shared__ float ssum[2][QT];
    __shared__ float sinvs[QT];
    const uint32_t sb = s2u(smem);
    const int t = threadIdx.x;
    const int wid = t >> 5, lane = t & 31;
    const int g = lane >> 2, m = lane & 3;
    const int qt = wid >> 1, half = wid & 1;
    const int bh = blockIdx.y, b = bh >> 3, h = bh & 7;
    const int qbase = blockIdx.x * QT;
    const int r1 = qt*16 + g, r2 = r1 + 8;
    const float INVSCALE = 0.13258252147247766f;   // sqrt(9/512)

    // ldmatrix per-lane addressing
    const int lrow  = (lane & 7) + ((lane >> 3) & 1)*8;
    const int lcol  = (lane >> 4)*16;
    const int brow  = (lane & 7) + (lane >> 4)*8;
    const int bcol  = ((lane >> 3) & 1)*16;

    // prologue
    {
        const __nv_bfloat16* qs = g_qs + ((size_t)bh*LL + qbase)*128;
        #pragma unroll
        for (int j = 0; j < 6; j++) {                    // Q: [hi|lo|hi], 128 q x 24 f4
            int idx = t + j*512; int row = idx/24, p = idx%24; int sf = (p < 16) ? p : p - 16;
            cp16(sb + SQ_ + row*400 + p*16, qs + (size_t)row*128 + sf*8);
        }
        load_kvm(sb, 0, 0, bh, b, qbase, mask, t);
        CP_COMMIT();
        load_kvm(sb, 1, 64, bh, b, qbase, mask, t);
        CP_COMMIT();
    }

    uint32_t* Pp = (uint32_t*)(smem + SP_);
    const uint32_t qaddr = sb + SQ_ + (qt*16 + lrow)*400 + lcol;
    const uint32_t paddr = sb + SP_ + (qt*16 + lrow)*144 + lcol;
    float cacc[8][4] = {};
    float sumA = 0.f, sumB = 0.f;
    const size_t bhrow = (size_t)bh*LL + qbase;

    for (int tt = 0; tt < 16; tt++) {
        if (tt == 15) { CP_WAIT(0); } else { CP_WAIT(1); }
        __syncthreads();
        const int buf = tt & 1;
        const uint32_t kaddr = sb + (buf ? SK1_ : SK0_) + (half*32 + brow)*400 + bcol;
        const uint32_t vaddr = sb + (buf ? SV1_ : SV0_) + brow*144 + bcol;
        const int* Mp = (const int*)(smem + (buf ? SM1_ : SM0_));
        const int cb = tt*64;

        // ---- scores: own key half, 4 n-tiles x 12 k-steps ----
        float acc[4][4] = {};
        #pragma unroll
        for (int ks = 0; ks < 12; ks++) {
            uint32_t a0, a1, a2, a3;
            ldsm4(a0, a1, a2, a3, qaddr + ks*32);
            uint32_t b0, b1, b2, b3;
            ldsm4(b0, b1, b2, b3, kaddr + ks*32);             // nt 0,1
            MMA16816(acc[0], a0, a1, a2, a3, b0, b1);
            MMA16816(acc[1], a0, a1, a2, a3, b2, b3);
            ldsm4(b0, b1, b2, b3, kaddr + 16*400 + ks*32);    // nt 2,3
            MMA16816(acc[2], a0, a1, a2, a3, b0, b1);
            MMA16816(acc[3], a0, a1, a2, a3, b2, b3);
        }
        // ---- mask + exp + sums + attn(e) store + P(bf16) ----
        #pragma unroll
        for (int nt = 0; nt < 4; nt++) {
            const int keyc = half*32 + nt*8 + 2*m;
            int2 mA = *(const int2*)(Mp + r1*68 + keyc);
            int2 mB = *(const int2*)(Mp + r2*68 + keyc);
            float e00 = mA.x ? 0.f : __expf(acc[nt][0]*INVSCALE);
            float e01 = mA.y ? 0.f : __expf(acc[nt][1]*INVSCALE);
            float e10 = mB.x ? 0.f : __expf(acc[nt][2]*INVSCALE);
            float e11 = mB.y ? 0.f : __expf(acc[nt][3]*INVSCALE);
            sumA += e00 + e01; sumB += e10 + e11;
            *(float2*)(attn_out + (bhrow + r1)*LL + cb + keyc) = make_float2(e00, e01);
            *(float2*)(attn_out + (bhrow + r2)*LL + cb + keyc) = make_float2(e10, e11);
            Pp[r1*36 + (half*4 + nt)*4 + m] = pbf2(e00, e01);
            Pp[r2*36 + (half*4 + nt)*4 + m] = pbf2(e10, e11);
        }
        __syncwarp();
        // ---- PV: own 2 k-steps, all 8 d-tiles ----
        #pragma unroll
        for (int ksl = 0; ksl < 2; ksl++) {
            const int ks = half*2 + ksl;
            uint32_t a0, a1, a2, a3;
            ldsm4(a0, a1, a2, a3, paddr + ks*32);
            #pragma unroll
            for (int nt2 = 0; nt2 < 4; nt2++) {
                uint32_t b0, b1, b2, b3;
                ldsm4(b0, b1, b2, b3, vaddr + nt2*16*144 + ks*32);
                MMA16816(cacc[nt2*2+0], a0, a1, a2, a3, b0, b1);
                MMA16816(cacc[nt2*2+1], a0, a1, a2, a3, b2, b3);
            }
        }
        __syncthreads();
        if (tt + 2 < 16) { load_kvm(sb, buf, (tt+2)*64, bh, b, qbase, mask, t); CP_COMMIT(); }
    }

    // ---- row sums ----
    sumA += __shfl_xor_sync(~0u, sumA, 1); sumA += __shfl_xor_sync(~0u, sumA, 2);
    sumB += __shfl_xor_sync(~0u, sumB, 1); sumB += __shfl_xor_sync(~0u, sumB, 2);
    if (m == 0) { ssum[half][r1] = sumA; ssum[half][r2] = sumB; }
    __syncthreads();
    if (t < QT) sinvs[t] = 1.0f / (ssum[0][t] + ssum[1][t]);
    __syncthreads();

    // ---- fused normalization tail: rescale own 128x1024 e block (L2-hot) ----
    {
        float* ablk = attn_out + bhrow*LL;
        #pragma unroll 8
        for (int it = 0; it < 64; it++) {
            const int idx = it*512 + t;          // float4 index; fully coalesced
            const float iv = sinvs[idx >> 8];    // 256 float4 per row
            float4 v = *(float4*)(ablk + (size_t)idx*4);
            v.x *= iv; v.y *= iv; v.z *= iv; v.w *= iv;
            *(float4*)(ablk + (size_t)idx*4) = v;
        }
    }

    // ---- combine ctx halves through smem (K buffers free) ----
    float* cbuf = (float*)(smem + SK0_);    // pitch 66
    if (half == 0) {
        #pragma unroll
        for (int nt = 0; nt < 8; nt++) {
            *(float2*)(cbuf + r1*66 + nt*8 + 2*m) = make_float2(cacc[nt][0], cacc[nt][1]);
            *(float2*)(cbuf + r2*66 + nt*8 + 2*m) = make_float2(cacc[nt][2], cacc[nt][3]);
        }
    }
    __syncthreads();
    if (half == 1) {
        const float invA = sinvs[r1];
        const float invB = sinvs[r2];
        float* c1p = g_ctx + ((size_t)b*LL + qbase + r1)*HID + h*DH;
        float* c2p = g_ctx + ((size_t)b*LL + qbase + r2)*HID + h*DH;
        #pragma unroll
        for (int nt = 0; nt < 8; nt++) {
            float2 p1 = *(float2*)(cbuf + r1*66 + nt*8 + 2*m);
            float2 p2 = *(float2*)(cbuf + r2*66 + nt*8 + 2*m);
            *(float2*)(c1p + nt*8 + 2*m) = make_float2((p1.x + cacc[nt][0])*invA,
                                                       (p1.y + cacc[nt][1])*invA);
            *(float2*)(c2p + nt*8 + 2*m) = make_float2((p2.x + cacc[nt][2])*invB,
                                                       (p2.y + cacc[nt][3])*invB);
        }
    }
}

// =====================================================================
// Kernel 3: out = LN(ctx @ Wo + bo + residual). 1024 thr, 32 tokens/block
// =====================================================================
__global__ void outproj_kernel(const float* __restrict__ Qin, const float* __restrict__ Wo,
                               const float* __restrict__ bo, const float* __restrict__ lng,
                               const float* __restrict__ lnb, float* __restrict__ out) {
    extern __shared__ float osm[];
    float* sWo = osm;                 // 512*19
    float* scx = sWo + HID*DM;        // 32*512
    float* sx  = scx + 32*HID;        // 32*20
    const int t = threadIdx.x, warp = t >> 5, lane = t & 31;
    for (int i = t; i < HID*DM; i += 1024) sWo[i] = Wo[i];
    const int n = blockIdx.x*32 + warp;
    #pragma unroll
    for (int k = 0; k < 4; k++)
        *(float4*)(scx + warp*HID + lane*4 + 128*k) =
            *(const float4*)(g_ctx + (size_t)n*HID + lane*4 + 128*k);
    __syncthreads();

    float x = 0.f;
    if (lane < DM) {
        float a0 = 0.f, a1 = 0.f, a2 = 0.f, a3 = 0.f;
        const float* cs = scx + warp*HID;
        for (int i = 0; i < HID; i += 4) {
            a0 += cs[i+0]*sWo[(i+0)*DM + lane];
            a1 += cs[i+1]*sWo[(i+1)*DM + lane];
            a2 += cs[i+2]*sWo[(i+2)*DM + lane];
            a3 += cs[i+3]*sWo[(i+3)*DM + lane];
        }
        x = (a0+a1) + (a2+a3) + bo[lane] + Qin[(size_t)n*DM + lane];
        sx[warp*20 + lane] = x;
    }
    __syncwarp();
    if (lane < DM) {
        float mu = 0.f;
        #pragma unroll
        for (int j = 0; j < DM; j++) mu += sx[warp*20 + j];
        mu *= (1.0f/19.0f);
        float var = 0.f;
        #pragma unroll
        for (int j = 0; j < DM; j++) { float d = sx[warp*20 + j] - mu; var += d*d; }
        var *= (1.0f/19.0f);
        out[(size_t)n*DM + lane] = (x - mu)*rsqrtf(var + 1e-5f)*lng[lane] + lnb[lane];
    }
}

// =====================================================================
// Kernel 4: residual = Q
// =====================================================================
__global__ void copy_res_kernel(const float* __restrict__ Qin, float* __restrict__ dst) {
    const size_t i = ((size_t)blockIdx.x*256 + threadIdx.x)*4;
    *(float4*)(dst + i) = *(const float4*)(Qin + i);
}

// =====================================================================
extern "C" void kernel_launch(void* const* d_in, const int* in_sizes, int n_in,
                              void* d_out, int out_size) {
    const float* Q   = (const float*)d_in[0];
    const float* K   = (const float*)d_in[1];
    const float* V   = (const float*)d_in[2];
    const int*  mask = (const int*)d_in[3];
    const float* Wq  = (const float*)d_in[4];
    const float* bq  = (const float*)d_in[5];
    const float* Wk  = (const float*)d_in[6];
    const float* bk  = (const float*)d_in[7];
    const float* Wv  = (const float*)d_in[8];
    const float* bv  = (const float*)d_in[9];
    const float* Wo  = (const float*)d_in[10];
    const float* bo  = (const float*)d_in[11];
    const float* lng = (const float*)d_in[12];
    const float* lnb = (const float*)d_in[13];

    float* out  = (float*)d_out;
    float* attn = out + OUT_ELEMS;
    float* res  = attn + ATTN_ELEMS;

    cudaFuncSetAttribute(attn_kernel, cudaFuncAttributeMaxDynamicSharedMemorySize, ATT_SMEM);
    const int OUT_SMEM = (HID*DM + 32*HID + 32*20) * (int)sizeof(float);   // 107008
    cudaFuncSetAttribute(outproj_kernel, cudaFuncAttributeMaxDynamicSharedMemorySize, OUT_SMEM);

    proj_kernel<<<dim3(NTOK/32, 3), 256>>>(Q, K, V, Wq, Wk, Wv, bq, bk, bv);
    transpose_v_kernel<<<dim3(LL/128, BB*NH), 256>>>();
    attn_kernel<<<dim3(LL/QT, BB*NH), 512, ATT_SMEM>>>(mask, attn);
    outproj_kernel<<<NTOK/32, 1024, OUT_SMEM>>>(Q, Wo, bo, lng, lnb, out);
    copy_res_kernel<<<OUT_ELEMS/4/256, 256>>>(Q, res);
}